// round 1
// baseline (speedup 1.0000x reference)
#include <cuda_runtime.h>
#include <math.h>

#define CDIV(a,b) (((a)+(b)-1)/(b))

// Problem constants
constexpr int cN0 = 120000;
constexpr int cN1 = 20000;
constexpr int cN2 = 6000;
constexpr int cN3 = 1600;
constexpr int cB  = 64;
constexpr int cE1 = 480000;
constexpr int cE2 = 144000;
constexpr int cE3 = 38400;

// ---------------- scratch pool (no cudaMalloc allowed) ----------------
constexpr int AL64(int x) { return (x + 63) & ~63; }
constexpr int O_H1   = 0;
constexpr int O_AGG1 = O_H1   + AL64(cN1);
constexpr int O_DEG1 = O_AGG1 + cN1 * 64;
constexpr int O_X1   = O_DEG1 + AL64(cN1);
constexpr int O_H2   = O_X1   + cN1 * 64;
constexpr int O_AGG2 = O_H2   + cN2 * 64;
constexpr int O_DEG2 = O_AGG2 + cN2 * 64;
constexpr int O_X2   = O_DEG2 + AL64(cN2);
constexpr int O_H3   = O_X2   + cN2 * 64;
constexpr int O_AGG3 = O_H3   + cN3 * 64;
constexpr int O_DEG3 = O_AGG3 + cN3 * 128;
constexpr int O_X3   = O_DEG3 + AL64(cN3);
constexpr int O_H4   = O_X3   + cN3 * 128;
constexpr int POOLN  = O_H4   + 512 * 128;

__device__ float4 g_pool4[(POOLN + 3) / 4];
__device__ __forceinline__ float* pool() { return (float*)g_pool4; }

// ---------------- helpers ----------------
__device__ __forceinline__ void atomicMaxFloat(float* addr, float val) {
    if (val >= 0.0f)
        atomicMax((int*)addr, __float_as_int(val));
    else
        atomicMin((unsigned int*)addr, __float_as_uint(val));
}

__device__ __forceinline__ float eluf(float v) {
    return v > 0.0f ? v : expm1f(v);
}

// ---------------- generic kernels ----------------
__global__ void fill_pool_kernel(int off, float v, int n) {
    int t = blockIdx.x * blockDim.x + threadIdx.x;
    if (t < n) pool()[off + t] = v;
}

// finalize seg-max (-inf -> 0) and zero agg/deg buffers in one pass
__global__ void prep_kernel(int hoff, int hn, int aggoff, int aggn, int degoff, int degn) {
    int t = blockIdx.x * blockDim.x + threadIdx.x;
    float* P = pool();
    if (t < hn) {
        float v = P[hoff + t];
        if (!isfinite(v)) P[hoff + t] = 0.0f;
    }
    if (t < aggn) P[aggoff + t] = 0.0f;
    if (t < degn) P[degoff + t] = 0.0f;
}

__global__ void segmax_x0_kernel(const float* __restrict__ x, const int* __restrict__ cl) {
    int t = blockIdx.x * blockDim.x + threadIdx.x;
    if (t >= cN0) return;
    atomicMaxFloat(pool() + O_H1 + cl[t], x[t]);
}

__global__ void segmax_pool_kernel(int xoff, const int* __restrict__ cl, int outoff,
                                   int ntot, int shift) {
    int t = blockIdx.x * blockDim.x + threadIdx.x;
    if (t >= ntot) return;
    int n = t >> shift;
    int o = t & ((1 << shift) - 1);
    float* P = pool();
    atomicMaxFloat(P + outoff + (cl[n] << shift) + o, P[xoff + t]);
}

// ---------------- spline basis (shared inline) ----------------
// p = pseudo*4; lo = clip(floor(p),0,3); f = p-lo
// basis_s = prod_d (bit_d ? f_d : 1-f_d);  k_s = (lo0+b0) + 5(lo1+b1) + 25(lo2+b2)
__device__ __forceinline__ void load_pseudo(const float* __restrict__ ps, int e,
                                            float& f0, float& f1, float& f2, int& kbase) {
    float p0 = ps[e * 3 + 0] * 4.0f;
    float p1 = ps[e * 3 + 1] * 4.0f;
    float p2 = ps[e * 3 + 2] * 4.0f;
    float lo0 = fmaxf(fminf(floorf(p0), 3.0f), 0.0f);
    float lo1 = fmaxf(fminf(floorf(p1), 3.0f), 0.0f);
    float lo2 = fmaxf(fminf(floorf(p2), 3.0f), 0.0f);
    f0 = p0 - lo0; f1 = p1 - lo1; f2 = p2 - lo2;
    kbase = (int)lo0 + 5 * (int)lo1 + 25 * (int)lo2;
}

// ---------------- layer 1: in=1, out=64 ----------------
__global__ void edge_conv_l1(const int* __restrict__ edge, const float* __restrict__ ps,
                             const float* __restrict__ W /*125x64*/) {
    int gw = (blockIdx.x * blockDim.x + threadIdx.x) >> 5;
    if (gw >= cE1) return;
    int lane = threadIdx.x & 31;
    float f0, f1, f2; int kb;
    load_pseudo(ps, gw, f0, f1, f2, kb);
    float acc0 = 0.0f, acc1 = 0.0f;
#pragma unroll
    for (int s = 0; s < 8; s++) {
        float b0 = (s & 1) ? f0 : 1.0f - f0;
        float b1 = (s & 2) ? f1 : 1.0f - f1;
        float b2 = (s & 4) ? f2 : 1.0f - f2;
        float basis = b0 * b1 * b2;
        int k = kb + (s & 1) + 5 * ((s >> 1) & 1) + 25 * ((s >> 2) & 1);
        float2 w = *(const float2*)(W + k * 64 + 2 * lane);
        acc0 = fmaf(basis, w.x, acc0);
        acc1 = fmaf(basis, w.y, acc1);
    }
    int src = edge[gw];
    int dst = edge[cE1 + gw];
    float* P = pool();
    float xs = P[O_H1 + src];
    atomicAdd(P + O_AGG1 + dst * 64 + 2 * lane,     acc0 * xs);
    atomicAdd(P + O_AGG1 + dst * 64 + 2 * lane + 1, acc1 * xs);
    if (lane == 0) atomicAdd(P + O_DEG1 + dst, 1.0f);
}

__global__ void node_l1(const float* __restrict__ root /*1x64*/, const float* __restrict__ bias) {
    int t = blockIdx.x * blockDim.x + threadIdx.x;
    if (t >= cN1 * 64) return;
    int n = t >> 6, o = t & 63;
    float* P = pool();
    float acc = bias[o] + P[O_AGG1 + t] / fmaxf(P[O_DEG1 + n], 1.0f) + P[O_H1 + n] * root[o];
    P[O_X1 + t] = eluf(acc);
}

// ---------------- layer 2: in=64, out=64, warp per edge ----------------
__global__ void edge_conv_64_64(const int* __restrict__ edge, int E,
                                const float* __restrict__ ps,
                                const float* __restrict__ W /*125x64x64*/,
                                int xoff, int aggoff, int degoff) {
    __shared__ float sx[8][64];
    int gw = (blockIdx.x * blockDim.x + threadIdx.x) >> 5;
    if (gw >= E) return;
    int lane = threadIdx.x & 31;
    int wl = threadIdx.x >> 5;
    float* P = pool();

    float f0, f1, f2; int kb;
    load_pseudo(ps, gw, f0, f1, f2, kb);
    int src = edge[gw];
    int dst = edge[E + gw];

    float2 xv = ((const float2*)(P + xoff + src * 64))[lane];
    sx[wl][2 * lane]     = xv.x;
    sx[wl][2 * lane + 1] = xv.y;
    __syncwarp();

    float acc0 = 0.0f, acc1 = 0.0f;
    for (int s = 0; s < 8; s++) {
        float b0 = (s & 1) ? f0 : 1.0f - f0;
        float b1 = (s & 2) ? f1 : 1.0f - f1;
        float b2 = (s & 4) ? f2 : 1.0f - f2;
        float basis = b0 * b1 * b2;
        int k = kb + (s & 1) + 5 * ((s >> 1) & 1) + 25 * ((s >> 2) & 1);
        const float2* wp = (const float2*)(W + k * 4096) + lane;
#pragma unroll 16
        for (int i = 0; i < 64; i++) {
            float xb = sx[wl][i] * basis;
            float2 w = wp[i * 32];
            acc0 = fmaf(xb, w.x, acc0);
            acc1 = fmaf(xb, w.y, acc1);
        }
    }
    atomicAdd(P + aggoff + dst * 64 + 2 * lane,     acc0);
    atomicAdd(P + aggoff + dst * 64 + 2 * lane + 1, acc1);
    if (lane == 0) atomicAdd(P + degoff + dst, 1.0f);
}

// ---------------- layer 3: in=64, out=128, warp per edge ----------------
__global__ void edge_conv_64_128(const int* __restrict__ edge, int E,
                                 const float* __restrict__ ps,
                                 const float* __restrict__ W /*125x64x128*/,
                                 int xoff, int aggoff, int degoff) {
    __shared__ float sx[8][64];
    int gw = (blockIdx.x * blockDim.x + threadIdx.x) >> 5;
    if (gw >= E) return;
    int lane = threadIdx.x & 31;
    int wl = threadIdx.x >> 5;
    float* P = pool();

    float f0, f1, f2; int kb;
    load_pseudo(ps, gw, f0, f1, f2, kb);
    int src = edge[gw];
    int dst = edge[E + gw];

    float2 xv = ((const float2*)(P + xoff + src * 64))[lane];
    sx[wl][2 * lane]     = xv.x;
    sx[wl][2 * lane + 1] = xv.y;
    __syncwarp();

    float acc0 = 0.0f, acc1 = 0.0f, acc2 = 0.0f, acc3 = 0.0f;
    for (int s = 0; s < 8; s++) {
        float b0 = (s & 1) ? f0 : 1.0f - f0;
        float b1 = (s & 2) ? f1 : 1.0f - f1;
        float b2 = (s & 4) ? f2 : 1.0f - f2;
        float basis = b0 * b1 * b2;
        int k = kb + (s & 1) + 5 * ((s >> 1) & 1) + 25 * ((s >> 2) & 1);
        const float* wk = W + k * 8192;
#pragma unroll 8
        for (int i = 0; i < 64; i++) {
            float xb = sx[wl][i] * basis;
            float2 wa = *(const float2*)(wk + i * 128 + 2 * lane);
            float2 wb = *(const float2*)(wk + i * 128 + 64 + 2 * lane);
            acc0 = fmaf(xb, wa.x, acc0);
            acc1 = fmaf(xb, wa.y, acc1);
            acc2 = fmaf(xb, wb.x, acc2);
            acc3 = fmaf(xb, wb.y, acc3);
        }
    }
    atomicAdd(P + aggoff + dst * 128 + 2 * lane,      acc0);
    atomicAdd(P + aggoff + dst * 128 + 2 * lane + 1,  acc1);
    atomicAdd(P + aggoff + dst * 128 + 64 + 2 * lane,     acc2);
    atomicAdd(P + aggoff + dst * 128 + 64 + 2 * lane + 1, acc3);
    if (lane == 0) atomicAdd(P + degoff + dst, 1.0f);
}

// ---------------- node update: out = elu(agg/deg + h @ root + b), din=64 ----------------
__global__ void node_dense(int hoff, int aggoff, int degoff, int xoff,
                           const float* __restrict__ root, const float* __restrict__ bias,
                           int ntot, int shift) {
    int t = blockIdx.x * blockDim.x + threadIdx.x;
    if (t >= ntot) return;
    int n = t >> shift;
    int o = t & ((1 << shift) - 1);
    float* P = pool();
    const float* h = P + hoff + n * 64;
    float acc = bias[o] + P[aggoff + t] / fmaxf(P[degoff + n], 1.0f);
#pragma unroll 16
    for (int i = 0; i < 64; i++)
        acc = fmaf(h[i], root[(i << shift) + o], acc);
    P[xoff + t] = eluf(acc);
}

// ---------------- final MLP + log_softmax, one block per batch row ----------------
__global__ void fc_kernel(const float* __restrict__ w1, const float* __restrict__ b1,
                          const float* __restrict__ w2, const float* __restrict__ b2,
                          float* __restrict__ out) {
    __shared__ float xrow[1024];
    __shared__ float hrow[256];
    __shared__ float logits[10];
    __shared__ float red[2];
    int b = blockIdx.x;
    int t = threadIdx.x;  // 256 threads
    float* P = pool();
    for (int i = t; i < 1024; i += 256) xrow[i] = P[O_H4 + b * 1024 + i];
    __syncthreads();

    float acc = b1[t];
#pragma unroll 8
    for (int i = 0; i < 1024; i++)
        acc = fmaf(xrow[i], w1[i * 256 + t], acc);
    hrow[t] = eluf(acc);
    __syncthreads();

    if (t < 10) {
        float a = b2[t];
#pragma unroll 8
        for (int i = 0; i < 256; i++)
            a = fmaf(hrow[i], w2[i * 10 + t], a);
        logits[t] = a;
    }
    __syncthreads();
    if (t == 0) {
        float m = logits[0];
        for (int j = 1; j < 10; j++) m = fmaxf(m, logits[j]);
        float s = 0.0f;
        for (int j = 0; j < 10; j++) s += expf(logits[j] - m);
        red[0] = m;
        red[1] = logf(s);
    }
    __syncthreads();
    if (t < 10) out[b * 10 + t] = logits[t] - red[0] - red[1];
}

// ---------------- host ----------------
extern "C" void kernel_launch(void* const* d_in, const int* in_sizes, int n_in,
                              void* d_out, int out_size) {
    const float* x0      = (const float*)d_in[0];
    const int*   cl0     = (const int*)  d_in[1];
    const int*   edge1   = (const int*)  d_in[2];
    const float* pseudo1 = (const float*)d_in[3];
    const float* W1      = (const float*)d_in[4];
    const float* root1   = (const float*)d_in[5];
    const float* b1      = (const float*)d_in[6];
    const int*   cl1     = (const int*)  d_in[7];
    const int*   edge2   = (const int*)  d_in[8];
    const float* pseudo2 = (const float*)d_in[9];
    const float* W2      = (const float*)d_in[10];
    const float* root2   = (const float*)d_in[11];
    const float* b2      = (const float*)d_in[12];
    const int*   cl2     = (const int*)  d_in[13];
    const int*   edge3   = (const int*)  d_in[14];
    const float* pseudo3 = (const float*)d_in[15];
    const float* W3      = (const float*)d_in[16];
    const float* root3   = (const float*)d_in[17];
    const float* b3      = (const float*)d_in[18];
    const int*   cl3     = (const int*)  d_in[19];
    const float* fc1w    = (const float*)d_in[20];
    const float* fc1b    = (const float*)d_in[21];
    const float* fc2w    = (const float*)d_in[22];
    const float* fc2b    = (const float*)d_in[23];
    float* out = (float*)d_out;

    const int TB = 256;
    const float NEGINF = -INFINITY;

    // ---- stage 0: seg_max(x0, cluster0) -> h1 (N1,1) ----
    fill_pool_kernel<<<CDIV(cN1, TB), TB>>>(O_H1, NEGINF, cN1);
    segmax_x0_kernel<<<CDIV(cN0, TB), TB>>>(x0, cl0);
    prep_kernel<<<CDIV(cN1 * 64, TB), TB>>>(O_H1, cN1, O_AGG1, cN1 * 64, O_DEG1, cN1);

    // ---- layer 1 conv ----
    edge_conv_l1<<<CDIV(cE1 * 32, TB), TB>>>(edge1, pseudo1, W1);
    node_l1<<<CDIV(cN1 * 64, TB), TB>>>(root1, b1);

    // ---- stage 1: seg_max(x1, cluster1) -> h2 (N2,64) ----
    fill_pool_kernel<<<CDIV(cN2 * 64, TB), TB>>>(O_H2, NEGINF, cN2 * 64);
    segmax_pool_kernel<<<CDIV(cN1 * 64, TB), TB>>>(O_X1, cl1, O_H2, cN1 * 64, 6);
    prep_kernel<<<CDIV(cN2 * 64, TB), TB>>>(O_H2, cN2 * 64, O_AGG2, cN2 * 64, O_DEG2, cN2);

    // ---- layer 2 conv ----
    edge_conv_64_64<<<CDIV(cE2 * 32, TB), TB>>>(edge2, cE2, pseudo2, W2, O_H2, O_AGG2, O_DEG2);
    node_dense<<<CDIV(cN2 * 64, TB), TB>>>(O_H2, O_AGG2, O_DEG2, O_X2, root2, b2, cN2 * 64, 6);

    // ---- stage 2: seg_max(x2, cluster2) -> h3 (N3,64) ----
    fill_pool_kernel<<<CDIV(cN3 * 64, TB), TB>>>(O_H3, NEGINF, cN3 * 64);
    segmax_pool_kernel<<<CDIV(cN2 * 64, TB), TB>>>(O_X2, cl2, O_H3, cN2 * 64, 6);
    prep_kernel<<<CDIV(cN3 * 128, TB), TB>>>(O_H3, cN3 * 64, O_AGG3, cN3 * 128, O_DEG3, cN3);

    // ---- layer 3 conv ----
    edge_conv_64_128<<<CDIV(cE3 * 32, TB), TB>>>(edge3, cE3, pseudo3, W3, O_H3, O_AGG3, O_DEG3);
    node_dense<<<CDIV(cN3 * 128, TB), TB>>>(O_H3, O_AGG3, O_DEG3, O_X3, root3, b3, cN3 * 128, 7);

    // ---- stage 3: seg_max(x3, cluster3) -> h4 (512,128) ----
    fill_pool_kernel<<<CDIV(512 * 128, TB), TB>>>(O_H4, NEGINF, 512 * 128);
    segmax_pool_kernel<<<CDIV(cN3 * 128, TB), TB>>>(O_X3, cl3, O_H4, cN3 * 128, 7);
    prep_kernel<<<CDIV(512 * 128, TB), TB>>>(O_H4, 512 * 128, 0, 0, 0, 0);

    // ---- MLP head ----
    fc_kernel<<<cB, 256>>>(fc1w, fc1b, fc2w, fc2b, out);
}